// round 8
// baseline (speedup 1.0000x reference)
#include <cuda_runtime.h>
#include <math.h>

#define NB 256      // batch
#define CC 256      // channels
#define TT 64       // time
#define VV 25       // vertices
#define DD 10       // final SPD dim
#define OUTD 64
#define FEATD 100
#define NS 65       // 10 mean-sums + 55 gram upper-tri
#define BPS 32      // blocks per sample in kernel 1

// scratch (allocation-free rule). Non-atomic per-block partials:
// every element rewritten every launch -> no zeroing, graph-deterministic.
__device__ float g_P[NB * BPS * NS];     // 2.1 MB, L2-resident

// ---------------------------------------------------------------------------
// Kernel 1: per (n,c) row: temporal mean, project through Wc = W1@W2@W3,
// then block-local reduction of 8 rows' mean/Gram partials -> 65 plain stores.
// Streaming loop unchanged (at DRAM floor).
// ---------------------------------------------------------------------------
__global__ void __launch_bounds__(256)
meanproj_kernel(const float* __restrict__ x,
                const float* __restrict__ W1,
                const float* __restrict__ W2,
                const float* __restrict__ W3) {
    __shared__ float t15[VV * 15];
    __shared__ float sWc[VV * DD + 32];   // padded so lanes>=10 read safely
    __shared__ float sy8[8][DD];          // this block's 8 projected vectors

    const int tid = threadIdx.x;

    for (int e = tid; e < VV * 15; e += 256) {
        int i = e / 15, j = e % 15;
        float s = 0.f;
        #pragma unroll
        for (int k = 0; k < 20; k++) s += W1[i * 20 + k] * W2[k * 15 + j];
        t15[e] = s;
    }
    __syncthreads();
    for (int e = tid; e < VV * DD + 32; e += 256) {
        float s = 0.f;
        if (e < VV * DD) {
            int i = e / DD, j = e % DD;
            #pragma unroll
            for (int k = 0; k < 15; k++) s += t15[i * 15 + k] * W3[k * DD + j];
        }
        sWc[e] = s;
    }
    __syncthreads();

    const int warp = tid >> 5, lane = tid & 31;
    const int gw = blockIdx.x * 8 + warp;           // (n,c) row index

    float xm = 0.f;
    if (lane < VV) {
        const float* p = x + (size_t)gw * (TT * VV) + lane;
        float a0 = 0.f, a1 = 0.f, a2 = 0.f, a3 = 0.f;
        float a4 = 0.f, a5 = 0.f, a6 = 0.f, a7 = 0.f;
        #pragma unroll
        for (int t = 0; t < TT; t += 8) {
            a0 += __ldcs(&p[(t + 0) * VV]);
            a1 += __ldcs(&p[(t + 1) * VV]);
            a2 += __ldcs(&p[(t + 2) * VV]);
            a3 += __ldcs(&p[(t + 3) * VV]);
            a4 += __ldcs(&p[(t + 4) * VV]);
            a5 += __ldcs(&p[(t + 5) * VV]);
            a6 += __ldcs(&p[(t + 6) * VV]);
            a7 += __ldcs(&p[(t + 7) * VV]);
        }
        xm = (((a0 + a1) + (a2 + a3)) + ((a4 + a5) + (a6 + a7))) * (1.0f / TT);
    }

    float y = 0.f;
    #pragma unroll
    for (int v = 0; v < VV; v++) {
        float xv = __shfl_sync(0xffffffffu, xm, v);
        y += xv * sWc[v * DD + lane];               // lanes >=10 hit pad
    }
    if (lane < DD) sy8[warp][lane] = y;
    __syncthreads();

    // block-local partials -> 65 plain global stores
    if (tid < NS) {
        float s;
        if (tid < DD) {
            s = 0.f;
            #pragma unroll
            for (int c = 0; c < 8; c++) s += sy8[c][tid];
        } else {
            int e = tid - DD, p = 0;
            while (e >= DD - p) { e -= DD - p; p++; }
            int q = p + e;
            s = 0.f;
            #pragma unroll
            for (int c = 0; c < 8; c++) s += sy8[c][p] * sy8[c][q];
        }
        g_P[blockIdx.x * NS + tid] = s;
    }
}

// ---------------------------------------------------------------------------
// Kernel 2: ONE WARP per sample: reduce this sample's 32 partial records
// (L2-resident), build E = A/s - I with s = tr(A)/10, Mercator log(A)
// (pure FMA), FC.
// ---------------------------------------------------------------------------
__global__ void __launch_bounds__(32)
spd_kernel(const float* __restrict__ fcw, const float* __restrict__ fcb,
           float* __restrict__ out) {
    __shared__ float sS [NS];
    __shared__ float sE [DD * 16];        // row-padded to 16 for float4 reads
    __shared__ float sL [FEATD];

    const int n    = blockIdx.x;
    const int lane = threadIdx.x;
    const float* gp = g_P + (size_t)n * BPS * NS;

    // lane l reduces sums {l, l+32, l+64} over the 32 partial records.
    // Fully unrolled -> 32 independent L2 loads in flight per sum.
    #pragma unroll
    for (int h = 0; h < 3; h++) {
        const int i = lane + h * 32;
        if (i < NS) {
            float s = 0.f;
            #pragma unroll
            for (int b = 0; b < BPS; b++) s += gp[b * NS + i];
            sS[i] = s;
        }
    }
    __syncwarp();

    // s = tr(A)/10 (all lanes redundantly); A = (G - C m m^T)/(C-1) + 1e-8 I
    float s_tr = 0.f;
    #pragma unroll
    for (int i = 0; i < DD; i++) {
        int idx = DD + 10 * i - (i * (i - 1)) / 2;
        float mi = sS[i] * (1.0f / CC);
        s_tr += sS[idx] - (float)CC * mi * mi;
    }
    s_tr = s_tr * (1.0f / (CC - 1)) * 0.1f + 1e-8f;
    const float inv_s = __fdividef(1.f, s_tr);
    const float logs  = __logf(s_tr);

    // build E = A/s - I; lane i owns row i
    float Prow[DD], acc[DD];
    if (lane < DD) {
        const float mi = sS[lane] * (1.0f / CC);
        #pragma unroll
        for (int j = 0; j < DD; j++) {
            int p = lane < j ? lane : j;
            int q = lane < j ? j : lane;
            int idx = DD + 10 * p - (p * (p - 1)) / 2 + (q - p);
            float mj = sS[j] * (1.0f / CC);
            float a = (sS[idx] - (float)CC * mi * mj) * (1.0f / (CC - 1))
                    + ((lane == j) ? 1e-8f : 0.f);
            float e = a * inv_s - ((lane == j) ? 1.f : 0.f);
            sE[lane * 16 + j] = e;
            Prow[j] = e;
            acc[j]  = e;
        }
    }
    __syncwarp();

    // Mercator series: 17 dependent 10x10 matmuls, pure FMA
    if (lane < DD) {
        float sign = -1.f;
        #pragma unroll 1
        for (int k = 2; k <= 18; k++) {
            float nP[DD];
            #pragma unroll
            for (int j = 0; j < DD; j++) nP[j] = 0.f;
            #pragma unroll
            for (int t = 0; t < DD; t++) {
                const float pv = Prow[t];
                const float4* er = (const float4*)&sE[t * 16];
                float4 e0 = er[0], e1 = er[1];
                float4 e2 = er[2];
                nP[0] += pv * e0.x; nP[1] += pv * e0.y;
                nP[2] += pv * e0.z; nP[3] += pv * e0.w;
                nP[4] += pv * e1.x; nP[5] += pv * e1.y;
                nP[6] += pv * e1.z; nP[7] += pv * e1.w;
                nP[8] += pv * e2.x; nP[9] += pv * e2.y;
            }
            const float coef = sign * __fdividef(1.f, (float)k);
            #pragma unroll
            for (int j = 0; j < DD; j++) {
                Prow[j] = nP[j];
                acc[j] += coef * nP[j];
            }
            sign = -sign;
        }
        #pragma unroll
        for (int j = 0; j < DD; j++)
            sL[lane * DD + j] = acc[j] + ((lane == j) ? logs : 0.f);
    }
    __syncwarp();

    // FC: each lane computes outputs m = lane and lane+32
    #pragma unroll
    for (int h = 0; h < 2; h++) {
        const int mo = lane + h * 32;
        float s = fcb[mo];
        const float* wr = fcw + mo * FEATD;
        #pragma unroll 5
        for (int f = 0; f < FEATD; f++) s += sL[f] * wr[f];
        out[n * OUTD + mo] = s;
    }
}

// ---------------------------------------------------------------------------
extern "C" void kernel_launch(void* const* d_in, const int* in_sizes, int n_in,
                              void* d_out, int out_size) {
    const float *x = nullptr, *W1 = nullptr, *W2 = nullptr, *W3 = nullptr;
    const float *fcw = nullptr, *fcb = nullptr;
    for (int i = 0; i < n_in; i++) {
        switch (in_sizes[i]) {
            case NB * CC * TT * VV: x   = (const float*)d_in[i]; break;
            case 500:               W1  = (const float*)d_in[i]; break;
            case 300:               W2  = (const float*)d_in[i]; break;
            case 150:               W3  = (const float*)d_in[i]; break;
            case 6400:              fcw = (const float*)d_in[i]; break;
            case 64:                fcb = (const float*)d_in[i]; break;
            default: break;
        }
    }

    // one warp per (n,c) row: 65536 rows -> 8192 blocks x 8 warps
    meanproj_kernel<<<(NB * CC) / 8, 256>>>(x, W1, W2, W3);

    // one warp per sample
    spd_kernel<<<NB, 32>>>(fcw, fcb, (float*)d_out);
}